// round 12
// baseline (speedup 1.0000x reference)
#include <cuda_runtime.h>
#include <math.h>
#include <stdint.h>

// Problem dims
#define BB 128
#define TT 512
#define II 300
#define HH 256
#define G4 1024   // 4*H

// persist geometry
#define CL 8           // CTAs per cluster
#define NCLUS 16       // clusters
#define PS 9           // ps batch stride (9 coprime 32 -> conflict-free)
#define HB_BYTES 8192u // bytes received per h buffer per step (8 CTAs x 1024 B)

// smem float-index layout for lstm_persist
//  [0..4)            : two mbarriers (16 B)
//  [4..4+4096)       : h_s [2 buf][8 rank][8 batch][32 unit]
//  [4100.. +512)     : stg [2 buf][8 batch][32 unit]   (1024 B each, 16B aligned)
//  [4612.. +9216)    : ps  [8 ks][128 row][PS]
#define HSF 4
#define STGF (HSF + 4096)
#define PSF (STGF + 512)
#define SMEM_FLOATS (PSF + 8 * 128 * PS)

// Scratch (device globals — no allocations allowed)
__device__ float g_xp[(size_t)TT * BB * G4];   // [t][b][gate]  (256 MB)
__device__ float g_hb[BB * HH];                // backward-dir final hidden

__device__ __forceinline__ float fast_sigmoid(float v) {
    return 1.0f / (1.0f + __expf(-v));
}
__device__ __forceinline__ float fast_tanh(float v) {
    return __fdividef(2.0f, 1.0f + __expf(-2.0f * v)) - 1.0f;
}

// packed dual-fp32 FMA
__device__ __forceinline__ void fma2(float2& acc, float2 a, float2 b) {
    asm("fma.rn.f32x2 %0, %1, %2, %0;"
        : "+l"(reinterpret_cast<unsigned long long&>(acc))
        : "l"(reinterpret_cast<unsigned long long&>(a)),
          "l"(reinterpret_cast<unsigned long long&>(b)));
}

__device__ __forceinline__ uint32_t mapa_u32(uint32_t saddr, uint32_t trank) {
    uint32_t ra;
    asm("mapa.shared::cluster.u32 %0, %1, %2;" : "=r"(ra) : "r"(saddr), "r"(trank));
    return ra;
}

// bulk async copy: local smem -> peer smem, complete_tx at peer's mbarrier
__device__ __forceinline__ void bulk_s2s(uint32_t dst, uint32_t src,
                                         uint32_t bytes, uint32_t mbar) {
    asm volatile(
        "cp.async.bulk.shared::cluster.shared::cta.mbarrier::complete_tx::bytes "
        "[%0], [%1], %2, [%3];"
        :: "r"(dst), "r"(src), "r"(bytes), "r"(mbar) : "memory");
}

__device__ __forceinline__ void mbar_init(uint32_t mb, uint32_t count) {
    asm volatile("mbarrier.init.shared.b64 [%0], %1;" :: "r"(mb), "r"(count) : "memory");
}
__device__ __forceinline__ void mbar_arrive_expect_tx(uint32_t mb, uint32_t bytes) {
    asm volatile("mbarrier.arrive.expect_tx.shared.b64 _, [%0], %1;"
                 :: "r"(mb), "r"(bytes) : "memory");
}
__device__ __forceinline__ void mbar_wait_cluster(uint32_t mb, uint32_t parity) {
    asm volatile(
        "{\n\t.reg .pred p;\n\t"
        "WL_%=:\n\t"
        "mbarrier.try_wait.parity.acquire.cluster.shared::cta.b64 p, [%0], %1, 0x989680;\n\t"
        "@p bra.uni WD_%=;\n\t"
        "bra.uni WL_%=;\n\t"
        "WD_%=:\n\t}"
        :: "r"(mb), "r"(parity) : "memory");
}

// ---------------------------------------------------------------------------
// xp GEMM: xp[t][b][n] = sum_i x[b][t][i] * W_ih_f[n][i] + b_f[n]
// ---------------------------------------------------------------------------
__global__ void xp_gemm(const float* __restrict__ A,
                        const float* __restrict__ W,
                        const float* __restrict__ bias) {
    __shared__ float As[8][132];
    __shared__ float Bs[8][132];

    const int nt = blockIdx.x;
    const int mt = blockIdx.y;
    const int tid = threadIdx.x;
    const int tx = tid & 15;
    const int ty = tid >> 4;

    const int m0 = mt * 128;
    const int n0 = nt * 128;

    float2 acc2[4][8];
#pragma unroll
    for (int ip = 0; ip < 4; ip++)
#pragma unroll
        for (int j = 0; j < 8; j++) acc2[ip][j] = make_float2(0.f, 0.f);

    for (int k0 = 0; k0 < II; k0 += 8) {
#pragma unroll
        for (int e = tid; e < 1024; e += 256) {
            int r = e >> 3;
            int kk = e & 7;
            int k = k0 + kk;
            As[kk][r] = (k < II) ? A[(size_t)(m0 + r) * II + k] : 0.0f;
            Bs[kk][r] = (k < II) ? W[(size_t)(n0 + r) * II + k] : 0.0f;
        }
        __syncthreads();

#pragma unroll
        for (int kk = 0; kk < 8; kk++) {
            float4 a0 = *(const float4*)&As[kk][ty * 8];
            float4 a1 = *(const float4*)&As[kk][ty * 8 + 4];
            float4 b0 = *(const float4*)&Bs[kk][tx * 8];
            float4 b1 = *(const float4*)&Bs[kk][tx * 8 + 4];
            float2 ap[4] = { {a0.x, a0.y}, {a0.z, a0.w}, {a1.x, a1.y}, {a1.z, a1.w} };
            float bj[8] = { b0.x, b0.y, b0.z, b0.w, b1.x, b1.y, b1.z, b1.w };
#pragma unroll
            for (int j = 0; j < 8; j++) {
                float2 bb = make_float2(bj[j], bj[j]);
#pragma unroll
                for (int ip = 0; ip < 4; ip++) fma2(acc2[ip][j], ap[ip], bb);
            }
        }
        __syncthreads();
    }

#pragma unroll
    for (int i = 0; i < 8; i++) {
        int m = m0 + ty * 8 + i;
        int bidx = m >> 9;
        int t = m & 511;
        size_t base = ((size_t)t * BB + bidx) * G4;
#pragma unroll
        for (int j = 0; j < 8; j++) {
            int n = n0 + tx * 8 + j;
            float v = (i & 1) ? acc2[i >> 1][j].y : acc2[i >> 1][j].x;
            g_xp[base + n] = v + bias[n];
        }
    }
}

// ---------------------------------------------------------------------------
// Backward direction: only ONE step matters (h0=c0=0 on x[:, T-1]).
// ---------------------------------------------------------------------------
__global__ void bwd_last(const float* __restrict__ x,
                         const float* __restrict__ Wb,
                         const float* __restrict__ bb) {
    const int b = blockIdx.x;
    const int tid = threadIdx.x;
    __shared__ float xs[304];
    __shared__ float gs[G4];

    const float* xr = x + ((size_t)b * TT + (TT - 1)) * II;
    for (int i = tid; i < II; i += 256) xs[i] = xr[i];
    __syncthreads();

    const int wid = tid >> 5;
    const int lane = tid & 31;
    for (int r = wid; r < G4; r += 8) {
        float s = 0.0f;
        const float* wr = Wb + (size_t)r * II;
        for (int i = lane; i < II; i += 32) s += xs[i] * wr[i];
#pragma unroll
        for (int off = 16; off > 0; off >>= 1)
            s += __shfl_down_sync(0xffffffffu, s, off);
        if (lane == 0) gs[r] = s + bb[r];
    }
    __syncthreads();

    if (tid < HH) {
        float ig = 1.0f / (1.0f + expf(-gs[tid]));
        float gg = tanhf(gs[512 + tid]);
        float og = 1.0f / (1.0f + expf(-gs[768 + tid]));
        float c = ig * gg;
        g_hb[b * HH + tid] = og * tanhf(c);
    }
}

// ---------------------------------------------------------------------------
// Persistent forward recurrence: 16 clusters x 8 CTAs; cluster = 8 batches.
// W in registers. NEW vs R11: h exchange is 8 cp.async.bulk copies per step
// (1024 B contiguous per peer; h layout [rank][batch][unit]) instead of 1024
// scalar st.async messages — per-target mbarrier updates drop 1024 -> 8,
// removing the serialized tx-count bottleneck. Final linear layer is fused
// as an epilogue (after the drain, every CTA's h buffer 0 holds the complete
// final h; rank 0 emits its cluster's 8x2 outputs).
// Protocol safety: identical structure to R9-R11 (rearm precedes own sends;
// peers' t+1 sends require my t sends; stg double-buffer reuse at t+2 is
// ordered behind all my t bulks having fully read stg).
// ---------------------------------------------------------------------------
__global__ void __launch_bounds__(512, 1) __cluster_dims__(CL, 1, 1)
lstm_persist(const float* __restrict__ Whh,
             const float* __restrict__ Wlin,
             const float* __restrict__ blin,
             float* __restrict__ out) {
    extern __shared__ float sm[];
    float* h_s = sm + HSF;                    // [2][8][8][32]
    float* stg = sm + STGF;                   // [2][8][32]
    float* ps  = sm + PSF;                    // [8][128][PS]

    const int tid = threadIdx.x;
    uint32_t rank;
    asm("mov.u32 %0, %%cluster_ctarank;" : "=r"(rank));
    const int cid = blockIdx.x >> 3;

    const uint32_t smem_base = (uint32_t)__cvta_generic_to_shared(sm);
    const uint32_t mb0 = smem_base;           // mbarrier for h buffer 0
    const uint32_t mb1 = smem_base + 8;       // mbarrier for h buffer 1
    const uint32_t hby = smem_base + HSF * 4;   // h_s byte addr
    const uint32_t stgby = smem_base + STGF * 4; // stg byte addr

    const int rr = tid & 63;                  // base row pair
    const int ks = tid >> 6;                  // 0..7 K chunk == source rank block
    const int gb = tid >> 5;                  // finalize: batch (tid<256)
    const int gu = tid & 31;                  // finalize: hidden unit
    const int kglob = (int)rank * 32 + gu;

    // ---- W rows into registers (once) ----
    const int grow0 = (rr >> 5) * HH + (int)rank * 32 + (rr & 31);          // gates 0/1
    const int grow1 = ((rr + 64) >> 5) * HH + (int)rank * 32 + (rr & 31);   // gates 2/3
    float2 w0p[16], w1p[16];
    {
        const float2* w0 = (const float2*)(Whh + (size_t)grow0 * HH + ks * 32);
        const float2* w1 = (const float2*)(Whh + (size_t)grow1 * HH + ks * 32);
#pragma unroll
        for (int i = 0; i < 16; i++) { w0p[i] = __ldg(&w0[i]); w1p[i] = __ldg(&w1[i]); }
    }

    // xp base for this thread's (batch, unit); stride per t is BB*G4
    const size_t xstep = (size_t)BB * G4;
    const float* xp_base = g_xp + (size_t)(cid * 8 + gb) * G4 + kglob;

    // preload xp for t=0
    float xi = 0.f, xf = 0.f, xg = 0.f, xo = 0.f;
    if (tid < 256) {
        xi = __ldg(xp_base + 0);
        xf = __ldg(xp_base + 256);
        xg = __ldg(xp_base + 512);
        xo = __ldg(xp_base + 768);
    }

    // zero h buffer 0; init mbarriers; arm mbar1 for step-0 sends
    for (int i = tid; i < 2048; i += 512) h_s[i] = 0.0f;
    if (tid == 0) {
        mbar_init(mb0, 1);
        mbar_init(mb1, 1);
        mbar_arrive_expect_tx(mb1, HB_BYTES);
    }
    __syncthreads();
    // one-time cluster barrier: all peers' mbarriers initialized+armed
    asm volatile("barrier.cluster.arrive.aligned;" ::: "memory");
    asm volatile("barrier.cluster.wait.aligned;" ::: "memory");

    float c_reg = 0.0f;
    int ph0 = 0, ph1 = 0;

    for (int t = 0; t < TT; t++) {
        const int cur = t & 1;
        const int nxt = cur ^ 1;

        // wait for this step's h (skip t=0: buffer 0 pre-zeroed, no sends)
        if (t > 0) {
            if (cur) { mbar_wait_cluster(mb1, (uint32_t)ph1); ph1 ^= 1; }
            else     { mbar_wait_cluster(mb0, (uint32_t)ph0); ph0 ^= 1; }
        }

        // issue NEXT step's xp loads now (full-step latency cover)
        float nxi = 0.f, nxf = 0.f, nxg = 0.f, nxo = 0.f;
        if (tid < 256 && t + 1 < TT) {
            const float* nb = xp_base + (size_t)(t + 1) * xstep;
            nxi = __ldg(nb + 0);
            nxf = __ldg(nb + 256);
            nxg = __ldg(nb + 512);
            nxo = __ldg(nb + 768);
        }

        // h block for this thread's K chunk: [cur][ks][batch][unit]
        const float* __restrict__ hb = h_s + cur * 2048 + ks * 256;

        // mainloop: 2 rows x 8 batches x 32 k, W in registers
#pragma unroll
        for (int w = 0; w < 2; w++) {
            float2 a0[4], a1[4];
#pragma unroll
            for (int j = 0; j < 4; j++) {
                a0[j] = make_float2(0.f, 0.f);
                a1[j] = make_float2(0.f, 0.f);
            }
#pragma unroll
            for (int k4 = 0; k4 < 8; k4++) {
                float2 wl0 = w0p[k4 * 2], wh0 = w0p[k4 * 2 + 1];
                float2 wl1 = w1p[k4 * 2], wh1 = w1p[k4 * 2 + 1];
#pragma unroll
                for (int j = 0; j < 4; j++) {
                    float4 hv = *(const float4*)(hb + (w * 4 + j) * 32 + k4 * 4);
                    float2 hl = make_float2(hv.x, hv.y);
                    float2 hh = make_float2(hv.z, hv.w);
                    fma2(a0[j], wl0, hl);
                    fma2(a0[j], wh0, hh);
                    fma2(a1[j], wl1, hl);
                    fma2(a1[j], wh1, hh);
                }
            }
#pragma unroll
            for (int j = 0; j < 4; j++) {
                ps[(ks * 128 + rr) * PS + w * 4 + j]      = a0[j].x + a0[j].y;
                ps[(ks * 128 + rr + 64) * PS + w * 4 + j] = a1[j].x + a1[j].y;
            }
        }
        __syncthreads();   // ps complete; all reads of h_s[cur] done

        // re-arm mbar[cur] for its next receive cycle (arrivals during t+1)
        if (tid == 0) {
            if (cur) mbar_arrive_expect_tx(mb1, HB_BYTES);
            else     mbar_arrive_expect_tx(mb0, HB_BYTES);
        }

        // finalize: reduce 8 k-chunks, gates, stage h, one bulk per peer
        if (tid < 256) {
            float pi = xi, pf = xf, pg = xg, po = xo;
#pragma unroll
            for (int s = 0; s < 8; s++) {
                const float* pp = &ps[(s * 128) * PS];
                pi += pp[(gu) * PS + gb];
                pf += pp[(32 + gu) * PS + gb];
                pg += pp[(64 + gu) * PS + gb];
                po += pp[(96 + gu) * PS + gb];
            }
            float ig = fast_sigmoid(pi);
            float fg = fast_sigmoid(pf);
            float gg = fast_tanh(pg);
            float og = fast_sigmoid(po);
            c_reg = fg * c_reg + ig * gg;
            float h = og * fast_tanh(c_reg);

            stg[nxt * 256 + gb * 32 + gu] = h;
            asm volatile("bar.sync 1, 256;" ::: "memory");

            if (tid == 0) {
                asm volatile("fence.proxy.async.shared::cta;" ::: "memory");
                uint32_t srcb = stgby + (uint32_t)(nxt * 1024);
                uint32_t dstoff = hby + (uint32_t)((nxt * 2048 + (int)rank * 256) * 4);
                uint32_t mboff = nxt ? mb1 : mb0;
#pragma unroll
                for (int r = 0; r < CL; r++) {
                    bulk_s2s(mapa_u32(dstoff, (uint32_t)r), srcb, 1024u,
                             mapa_u32(mboff, (uint32_t)r));
                }
            }
        }
        // rotate xp double buffer
        xi = nxi; xf = nxf; xg = nxg; xo = nxo;
        // no cluster barrier: next iteration's mbar wait is the sync point
    }

    // drain incoming step-511 sends (into buffer 0): afterwards EVERY CTA's
    // h buffer 0 holds the complete final h for all 8 batches
    mbar_wait_cluster(mb0, (uint32_t)ph0);

    // fused final linear: rank 0 emits this cluster's 8 batches x 2 outputs.
    // warp w -> (batch w>>1, output j=w&1); lane covers 32 units x 8 ranks.
    if (rank == 0) {
        int w = tid >> 5;
        int lane = tid & 31;
        int bw = w >> 1;
        int j = w & 1;
        float s = 0.f;
#pragma unroll
        for (int i = 0; i < 8; i++) {
            float hf = h_s[i * 256 + bw * 32 + lane];          // unit i*32+lane
            s += hf * Wlin[j * 512 + i * 32 + lane];
            float hbv = g_hb[(cid * 8 + bw) * HH + i * 32 + lane];
            s += hbv * Wlin[j * 512 + 256 + i * 32 + lane];
        }
#pragma unroll
        for (int off = 16; off > 0; off >>= 1)
            s += __shfl_down_sync(0xffffffffu, s, off);
        if (lane == 0) out[(cid * 8 + bw) * 2 + j] = s + blin[j];
    }
}

// ---------------------------------------------------------------------------
extern "C" void kernel_launch(void* const* d_in, const int* in_sizes, int n_in,
                              void* d_out, int out_size) {
    const float* x      = (const float*)d_in[0];
    const float* W_ih_f = (const float*)d_in[1];
    const float* W_hh_f = (const float*)d_in[2];
    const float* b_f    = (const float*)d_in[3];
    const float* W_ih_b = (const float*)d_in[4];
    // d_in[5] = W_hh_b : unused (backward dir needs only its first step, h0=0)
    const float* b_b    = (const float*)d_in[6];
    const float* W_lin  = (const float*)d_in[7];
    const float* b_lin  = (const float*)d_in[8];
    float* out = (float*)d_out;

    const int smem_bytes = SMEM_FLOATS * 4;   // 55312
    cudaFuncSetAttribute(lstm_persist,
                         cudaFuncAttributeMaxDynamicSharedMemorySize, smem_bytes);

    xp_gemm<<<dim3(8, 512), 256>>>(x, W_ih_f, b_f);
    bwd_last<<<BB, 256>>>(x, W_ih_b, b_b);
    lstm_persist<<<NCLUS * CL, 512, smem_bytes>>>(W_hh_f, W_lin, b_lin, out);
}

// round 13
// speedup vs baseline: 1.1471x; 1.1471x over previous
#include <cuda_runtime.h>
#include <mma.h>
#include <math.h>
#include <stdint.h>

using namespace nvcuda;

// Problem dims
#define BB 128
#define TT 512
#define II 300
#define HH 256
#define G4 1024   // 4*H

// persist geometry
#define CL 8           // CTAs per cluster
#define NCLUS 16       // clusters
#define PS 9           // ps batch stride (9 coprime 32 -> conflict-free)
#define HB_BYTES 8192u // bytes received per h buffer per step (8 CTAs x 1024 B)

// smem float-index layout for lstm_persist
#define HSF 4
#define STGF (HSF + 4096)
#define PSF (STGF + 512)
#define SMEM_FLOATS (PSF + 8 * 128 * PS)

// Scratch (device globals — no allocations allowed)
__device__ float g_xp[(size_t)TT * BB * G4];   // [t][b][gate]  (256 MB), NO bias
__device__ float g_hb[BB * HH];                // backward-dir final hidden

__device__ __forceinline__ float fast_sigmoid(float v) {
    return 1.0f / (1.0f + __expf(-v));
}
__device__ __forceinline__ float fast_tanh(float v) {
    return __fdividef(2.0f, 1.0f + __expf(-2.0f * v)) - 1.0f;
}

// packed dual-fp32 FMA
__device__ __forceinline__ void fma2(float2& acc, float2 a, float2 b) {
    asm("fma.rn.f32x2 %0, %1, %2, %0;"
        : "+l"(reinterpret_cast<unsigned long long&>(acc))
        : "l"(reinterpret_cast<unsigned long long&>(a)),
          "l"(reinterpret_cast<unsigned long long&>(b)));
}

__device__ __forceinline__ uint32_t mapa_u32(uint32_t saddr, uint32_t trank) {
    uint32_t ra;
    asm("mapa.shared::cluster.u32 %0, %1, %2;" : "=r"(ra) : "r"(saddr), "r"(trank));
    return ra;
}

// bulk async copy: local smem -> peer smem, complete_tx at peer's mbarrier
__device__ __forceinline__ void bulk_s2s(uint32_t dst, uint32_t src,
                                         uint32_t bytes, uint32_t mbar) {
    asm volatile(
        "cp.async.bulk.shared::cluster.shared::cta.mbarrier::complete_tx::bytes "
        "[%0], [%1], %2, [%3];"
        :: "r"(dst), "r"(src), "r"(bytes), "r"(mbar) : "memory");
}

__device__ __forceinline__ void mbar_init(uint32_t mb, uint32_t count) {
    asm volatile("mbarrier.init.shared.b64 [%0], %1;" :: "r"(mb), "r"(count) : "memory");
}
__device__ __forceinline__ void mbar_arrive_expect_tx(uint32_t mb, uint32_t bytes) {
    asm volatile("mbarrier.arrive.expect_tx.shared.b64 _, [%0], %1;"
                 :: "r"(mb), "r"(bytes) : "memory");
}
__device__ __forceinline__ void mbar_wait_cluster(uint32_t mb, uint32_t parity) {
    asm volatile(
        "{\n\t.reg .pred p;\n\t"
        "WL_%=:\n\t"
        "mbarrier.try_wait.parity.acquire.cluster.shared::cta.b64 p, [%0], %1, 0x989680;\n\t"
        "@p bra.uni WD_%=;\n\t"
        "bra.uni WL_%=;\n\t"
        "WD_%=:\n\t}"
        :: "r"(mb), "r"(parity) : "memory");
}

// ---------------------------------------------------------------------------
// xp GEMM via tf32 tensor cores (WMMA m16n16k8).
// xp[t][b][n] = sum_i x[b][t][i] * W_ih_f[n][i]      (bias added in persist)
// A = x as [M=65536][300] (m = b*512 + t), B = W [1024][300], both K-contig.
// CTA tile 128(M) x 64(N), 8 warps -> each 32x32 = 2x2 m16n16k8 frags.
// K staged in 32-chunks in smem (ldm 40); tail chunk zero-padded.
// C fragments store DIRECTLY to g_xp: within a 16-row m-tile the map
// m -> ((m&511)*128 + (m>>9))*1024 + n is linear with row stride 131072.
// ---------------------------------------------------------------------------
__global__ void __launch_bounds__(256) xp_gemm(const float* __restrict__ A,
                                               const float* __restrict__ W) {
    __shared__ float As[128 * 40];
    __shared__ float Bs[64 * 40];

    const int nt = blockIdx.x;           // 0..15
    const int mt = blockIdx.y;           // 0..511
    const int tid = threadIdx.x;
    const int wid = tid >> 5;

    const int m0 = mt * 128;
    const int n0 = nt * 64;

    const int mrow0 = (wid >> 1) * 32;   // warp's m offset in tile
    const int ncol0 = (wid & 1) * 32;    // warp's n offset in tile

    wmma::fragment<wmma::accumulator, 16, 16, 8, float> c[2][2];
#pragma unroll
    for (int i = 0; i < 2; i++)
#pragma unroll
        for (int j = 0; j < 2; j++) wmma::fill_fragment(c[i][j], 0.0f);

    const int ar = tid >> 1, ah = tid & 1;        // A: row, 16-col half
    const int br = tid >> 2, bq = tid & 3;        // B: row, 8-col quarter

    for (int k0 = 0; k0 < II; k0 += 32) {
        // stage A tile: 128 x 32
        if (k0 + 32 <= II) {
            const float4* src = (const float4*)(A + (size_t)(m0 + ar) * II + k0 + ah * 16);
            float4* dst = (float4*)(As + ar * 40 + ah * 16);
#pragma unroll
            for (int i = 0; i < 4; i++) dst[i] = src[i];
            const float4* s2 = (const float4*)(W + (size_t)(n0 + br) * II + k0 + bq * 8);
            float4* d2 = (float4*)(Bs + br * 40 + bq * 8);
            d2[0] = s2[0];
            d2[1] = s2[1];
        } else {
#pragma unroll
            for (int i = 0; i < 16; i++) {
                int k = k0 + ah * 16 + i;
                As[ar * 40 + ah * 16 + i] =
                    (k < II) ? A[(size_t)(m0 + ar) * II + k] : 0.0f;
            }
#pragma unroll
            for (int i = 0; i < 8; i++) {
                int k = k0 + bq * 8 + i;
                Bs[br * 40 + bq * 8 + i] =
                    (k < II) ? W[(size_t)(n0 + br) * II + k] : 0.0f;
            }
        }
        __syncthreads();

#pragma unroll
        for (int k8 = 0; k8 < 4; k8++) {
            wmma::fragment<wmma::matrix_a, 16, 16, 8, wmma::precision::tf32,
                           wmma::row_major> a[2];
            wmma::fragment<wmma::matrix_b, 16, 16, 8, wmma::precision::tf32,
                           wmma::col_major> b[2];
#pragma unroll
            for (int i = 0; i < 2; i++) {
                wmma::load_matrix_sync(a[i], As + (mrow0 + i * 16) * 40 + k8 * 8, 40);
#pragma unroll
                for (int e = 0; e < a[i].num_elements; e++)
                    a[i].x[e] = wmma::__float_to_tf32(a[i].x[e]);
            }
#pragma unroll
            for (int j = 0; j < 2; j++) {
                wmma::load_matrix_sync(b[j], Bs + (ncol0 + j * 16) * 40 + k8 * 8, 40);
#pragma unroll
                for (int e = 0; e < b[j].num_elements; e++)
                    b[j].x[e] = wmma::__float_to_tf32(b[j].x[e]);
            }
#pragma unroll
            for (int i = 0; i < 2; i++)
#pragma unroll
                for (int j = 0; j < 2; j++)
                    wmma::mma_sync(c[i][j], a[i], b[j], c[i][j]);
        }
        __syncthreads();
    }

    // direct store: tile of 16 consecutive m stays in one b (16 | 512);
    // row stride in g_xp is 128*1024 floats
#pragma unroll
    for (int i = 0; i < 2; i++) {
        int m = m0 + mrow0 + i * 16;
        int bidx = m >> 9;
        int t0 = m & 511;
#pragma unroll
        for (int j = 0; j < 2; j++) {
            int n = n0 + ncol0 + j * 16;
            float* dst = g_xp + ((size_t)t0 * BB + bidx) * G4 + n;
            wmma::store_matrix_sync(dst, c[i][j], 131072u, wmma::mem_row_major);
        }
    }
}

// ---------------------------------------------------------------------------
// Backward direction: only ONE step matters (h0=c0=0 on x[:, T-1]).
// ---------------------------------------------------------------------------
__global__ void bwd_last(const float* __restrict__ x,
                         const float* __restrict__ Wb,
                         const float* __restrict__ bb) {
    const int b = blockIdx.x;
    const int tid = threadIdx.x;
    __shared__ float xs[304];
    __shared__ float gs[G4];

    const float* xr = x + ((size_t)b * TT + (TT - 1)) * II;
    for (int i = tid; i < II; i += 256) xs[i] = xr[i];
    __syncthreads();

    const int wid = tid >> 5;
    const int lane = tid & 31;
    for (int r = wid; r < G4; r += 8) {
        float s = 0.0f;
        const float* wr = Wb + (size_t)r * II;
        for (int i = lane; i < II; i += 32) s += xs[i] * wr[i];
#pragma unroll
        for (int off = 16; off > 0; off >>= 1)
            s += __shfl_down_sync(0xffffffffu, s, off);
        if (lane == 0) gs[r] = s + bb[r];
    }
    __syncthreads();

    if (tid < HH) {
        float ig = 1.0f / (1.0f + expf(-gs[tid]));
        float gg = tanhf(gs[512 + tid]);
        float og = 1.0f / (1.0f + expf(-gs[768 + tid]));
        float c = ig * gg;
        g_hb[b * HH + tid] = og * tanhf(c);
    }
}

// ---------------------------------------------------------------------------
// Persistent forward recurrence (structure = R12): 16 clusters x 8 CTAs,
// W in registers, bulk h exchange + mbarrier complete_tx, double-buffered xp
// prefetch, fused final linear. NEW: adds b_f here (xp no longer carries it).
// ---------------------------------------------------------------------------
__global__ void __launch_bounds__(512, 1) __cluster_dims__(CL, 1, 1)
lstm_persist(const float* __restrict__ Whh,
             const float* __restrict__ bf,
             const float* __restrict__ Wlin,
             const float* __restrict__ blin,
             float* __restrict__ out) {
    extern __shared__ float sm[];
    float* h_s = sm + HSF;                    // [2][8][8][32]
    float* stg = sm + STGF;                   // [2][8][32]
    float* ps  = sm + PSF;                    // [8][128][PS]

    const int tid = threadIdx.x;
    uint32_t rank;
    asm("mov.u32 %0, %%cluster_ctarank;" : "=r"(rank));
    const int cid = blockIdx.x >> 3;

    const uint32_t smem_base = (uint32_t)__cvta_generic_to_shared(sm);
    const uint32_t mb0 = smem_base;
    const uint32_t mb1 = smem_base + 8;
    const uint32_t hby = smem_base + HSF * 4;
    const uint32_t stgby = smem_base + STGF * 4;

    const int rr = tid & 63;
    const int ks = tid >> 6;
    const int gb = tid >> 5;                  // finalize: batch (tid<256)
    const int gu = tid & 31;                  // finalize: hidden unit
    const int kglob = (int)rank * 32 + gu;

    // ---- W rows into registers (once) ----
    const int grow0 = (rr >> 5) * HH + (int)rank * 32 + (rr & 31);
    const int grow1 = ((rr + 64) >> 5) * HH + (int)rank * 32 + (rr & 31);
    float2 w0p[16], w1p[16];
    {
        const float2* w0 = (const float2*)(Whh + (size_t)grow0 * HH + ks * 32);
        const float2* w1 = (const float2*)(Whh + (size_t)grow1 * HH + ks * 32);
#pragma unroll
        for (int i = 0; i < 16; i++) { w0p[i] = __ldg(&w0[i]); w1p[i] = __ldg(&w1[i]); }
    }

    // per-thread gate biases (xp no longer has bias)
    float bfi = 0.f, bff = 0.f, bfg = 0.f, bfo = 0.f;
    if (tid < 256) {
        bfi = __ldg(&bf[kglob]);
        bff = __ldg(&bf[256 + kglob]);
        bfg = __ldg(&bf[512 + kglob]);
        bfo = __ldg(&bf[768 + kglob]);
    }

    const size_t xstep = (size_t)BB * G4;
    const float* xp_base = g_xp + (size_t)(cid * 8 + gb) * G4 + kglob;

    // preload xp for t=0
    float xi = 0.f, xf = 0.f, xg = 0.f, xo = 0.f;
    if (tid < 256) {
        xi = __ldg(xp_base + 0);
        xf = __ldg(xp_base + 256);
        xg = __ldg(xp_base + 512);
        xo = __ldg(xp_base + 768);
    }

    // zero h buffer 0; init mbarriers; arm mbar1 for step-0 sends
    for (int i = tid; i < 2048; i += 512) h_s[i] = 0.0f;
    if (tid == 0) {
        mbar_init(mb0, 1);
        mbar_init(mb1, 1);
        mbar_arrive_expect_tx(mb1, HB_BYTES);
    }
    __syncthreads();
    asm volatile("barrier.cluster.arrive.aligned;" ::: "memory");
    asm volatile("barrier.cluster.wait.aligned;" ::: "memory");

    float c_reg = 0.0f;
    int ph0 = 0, ph1 = 0;

    for (int t = 0; t < TT; t++) {
        const int cur = t & 1;
        const int nxt = cur ^ 1;

        if (t > 0) {
            if (cur) { mbar_wait_cluster(mb1, (uint32_t)ph1); ph1 ^= 1; }
            else     { mbar_wait_cluster(mb0, (uint32_t)ph0); ph0 ^= 1; }
        }

        // issue NEXT step's xp loads (full-step latency cover)
        float nxi = 0.f, nxf = 0.f, nxg = 0.f, nxo = 0.f;
        if (tid < 256 && t + 1 < TT) {
            const float* nb = xp_base + (size_t)(t + 1) * xstep;
            nxi = __ldg(nb + 0);
            nxf = __ldg(nb + 256);
            nxg = __ldg(nb + 512);
            nxo = __ldg(nb + 768);
        }

        const float* __restrict__ hb = h_s + cur * 2048 + ks * 256;

        // mainloop: 2 rows x 8 batches x 32 k, W in registers
#pragma unroll
        for (int w = 0; w < 2; w++) {
            float2 a0[4], a1[4];
#pragma unroll
            for (int j = 0; j < 4; j++) {
                a0[j] = make_float2(0.f, 0.f);
                a1[j] = make_float2(0.f, 0.f);
            }
#pragma unroll
            for (int k4 = 0; k4 < 8; k4++) {
                float2 wl0 = w0p[k4 * 2], wh0 = w0p[k4 * 2 + 1];
                float2 wl1 = w1p[k4 * 2], wh1 = w1p[k4 * 2 + 1];
#pragma unroll
                for (int j = 0; j < 4; j++) {
                    float4 hv = *(const float4*)(hb + (w * 4 + j) * 32 + k4 * 4);
                    float2 hl = make_float2(hv.x, hv.y);
                    float2 hh = make_float2(hv.z, hv.w);
                    fma2(a0[j], wl0, hl);
                    fma2(a0[j], wh0, hh);
                    fma2(a1[j], wl1, hl);
                    fma2(a1[j], wh1, hh);
                }
            }
#pragma unroll
            for (int j = 0; j < 4; j++) {
                ps[(ks * 128 + rr) * PS + w * 4 + j]      = a0[j].x + a0[j].y;
                ps[(ks * 128 + rr + 64) * PS + w * 4 + j] = a1[j].x + a1[j].y;
            }
        }
        __syncthreads();

        if (tid == 0) {
            if (cur) mbar_arrive_expect_tx(mb1, HB_BYTES);
            else     mbar_arrive_expect_tx(mb0, HB_BYTES);
        }

        // finalize: reduce 8 k-chunks, add xp+bias, gates, stage h, bulks
        if (tid < 256) {
            float pi = xi + bfi, pf = xf + bff, pg = xg + bfg, po = xo + bfo;
#pragma unroll
            for (int s = 0; s < 8; s++) {
                const float* pp = &ps[(s * 128) * PS];
                pi += pp[(gu) * PS + gb];
                pf += pp[(32 + gu) * PS + gb];
                pg += pp[(64 + gu) * PS + gb];
                po += pp[(96 + gu) * PS + gb];
            }
            float ig = fast_sigmoid(pi);
            float fg = fast_sigmoid(pf);
            float gg = fast_tanh(pg);
            float og = fast_sigmoid(po);
            c_reg = fg * c_reg + ig * gg;
            float h = og * fast_tanh(c_reg);

            stg[nxt * 256 + gb * 32 + gu] = h;
            asm volatile("bar.sync 1, 256;" ::: "memory");

            if (tid == 0) {
                asm volatile("fence.proxy.async.shared::cta;" ::: "memory");
                uint32_t srcb = stgby + (uint32_t)(nxt * 1024);
                uint32_t dstoff = hby + (uint32_t)((nxt * 2048 + (int)rank * 256) * 4);
                uint32_t mboff = nxt ? mb1 : mb0;
#pragma unroll
                for (int r = 0; r < CL; r++) {
                    bulk_s2s(mapa_u32(dstoff, (uint32_t)r), srcb, 1024u,
                             mapa_u32(mboff, (uint32_t)r));
                }
            }
        }
        xi = nxi; xf = nxf; xg = nxg; xo = nxo;
    }

    // drain step-511 sends: buffer 0 then holds the complete final h
    mbar_wait_cluster(mb0, (uint32_t)ph0);

    // fused final linear: rank 0 emits this cluster's 8 batches x 2 outputs
    if (rank == 0) {
        int w = tid >> 5;
        int lane = tid & 31;
        int bw = w >> 1;
        int j = w & 1;
        float s = 0.f;
#pragma unroll
        for (int i = 0; i < 8; i++) {
            float hf = h_s[i * 256 + bw * 32 + lane];
            s += hf * Wlin[j * 512 + i * 32 + lane];
            float hbv = g_hb[(cid * 8 + bw) * HH + i * 32 + lane];
            s += hbv * Wlin[j * 512 + 256 + i * 32 + lane];
        }
#pragma unroll
        for (int off = 16; off > 0; off >>= 1)
            s += __shfl_down_sync(0xffffffffu, s, off);
        if (lane == 0) out[(cid * 8 + bw) * 2 + j] = s + blin[j];
    }
}

// ---------------------------------------------------------------------------
extern "C" void kernel_launch(void* const* d_in, const int* in_sizes, int n_in,
                              void* d_out, int out_size) {
    const float* x      = (const float*)d_in[0];
    const float* W_ih_f = (const float*)d_in[1];
    const float* W_hh_f = (const float*)d_in[2];
    const float* b_f    = (const float*)d_in[3];
    const float* W_ih_b = (const float*)d_in[4];
    // d_in[5] = W_hh_b : unused (backward dir needs only its first step, h0=0)
    const float* b_b    = (const float*)d_in[6];
    const float* W_lin  = (const float*)d_in[7];
    const float* b_lin  = (const float*)d_in[8];
    float* out = (float*)d_out;

    const int smem_bytes = SMEM_FLOATS * 4;   // 55312
    cudaFuncSetAttribute(lstm_persist,
                         cudaFuncAttributeMaxDynamicSharedMemorySize, smem_bytes);

    xp_gemm<<<dim3(16, 512), 256>>>(x, W_ih_f);
    bwd_last<<<BB, 256>>>(x, W_ih_b, b_b);
    lstm_persist<<<NCLUS * CL, 512, smem_bytes>>>(W_hh_f, b_f, W_lin, b_lin, out);
}